// round 3
// baseline (speedup 1.0000x reference)
#include <cuda_runtime.h>
#include <cuda_bf16.h>
#include <math.h>

// Problem constants
#define BB 16
#define NN 256
#define HH 72
#define SS 13
#define NODES (BB*NN)          // 4096
#define EDGE_CNT ((float)(BB)*(float)(NN)*(float)(NN))  // 1048576
#define NSLOT 128

// Scratch (device globals; no allocation allowed)
__device__ float g_A[NODES*HH];
__device__ float g_Bv[NODES*HH];
__device__ float g_magg[NODES*HH];
__device__ float g_y[NODES*HH];
__device__ float g_esum[NSLOT*HH];
__device__ float g_esq[NSLOT*HH];
__device__ float g_nsum[NSLOT*HH];
__device__ float g_nsq[NSLOT*HH];
__device__ float g_scsh1[2*HH];
__device__ float g_scsh2[2*HH];

__device__ __forceinline__ float psif(float x) {
    return copysignf(log1pf(fabsf(x)), x);
}

// ---------------------------------------------------------------------------
// 0. zero slot accumulators
__global__ void k_zero() {
    int i = blockIdx.x * blockDim.x + threadIdx.x;
    if (i < NSLOT*HH) { g_esum[i]=0.f; g_esq[i]=0.f; g_nsum[i]=0.f; g_nsq[i]=0.f; }
}

// ---------------------------------------------------------------------------
// 1. node pre: A = h @ We1[0:72], Bv = h @ We1[72:144]
__global__ void k_nodepre(const float* __restrict__ h, const float* __restrict__ We1) {
    __shared__ float hs[HH];
    int node = blockIdx.x;
    int c = threadIdx.x;
    if (c < HH) hs[c] = h[node*HH + c];
    __syncthreads();
    if (c < HH) {
        float a = 0.f, b = 0.f;
        #pragma unroll 4
        for (int k = 0; k < HH; k++) {
            float hv = hs[k];
            a = fmaf(hv, We1[k*HH + c], a);
            b = fmaf(hv, We1[(k+HH)*HH + c], b);
        }
        g_A[node*HH + c] = a;
        g_Bv[node*HH + c] = b;
    }
}

// ---------------------------------------------------------------------------
// 2. edge stats: per-channel sum and sumsq of x over all B*N*N edges
__global__ void k_edgestats(const float* __restrict__ p, const float* __restrict__ We1) {
    __shared__ float ndn[NN], ndd[NN];
    __shared__ float sA[HH], su[HH], sv[HH];
    int node = blockIdx.x;           // (b,i)
    int b = node >> 8;
    int tid = threadIdx.x;           // 128 threads

    float4 pi4 = *(const float4*)(p + node*4);
    // n,d for all j
    for (int jj = tid; jj < NN; jj += 128) {
        float4 pj = *(const float4*)(p + ((b<<8) + jj)*4);
        float d0 = pi4.x - pj.x, d1 = pi4.y - pj.y, d2 = pi4.z - pj.z, d3 = pi4.w - pj.w;
        ndn[jj] = psif(-d0*d0 + d1*d1 + d2*d2 + d3*d3);
        ndd[jj] = psif(pi4.x*pj.x - pi4.y*pj.y - pi4.z*pj.z - pi4.w*pj.w);
    }
    if (tid < HH) {
        sA[tid] = g_A[node*HH + tid];
        su[tid] = We1[144*HH + tid];
        sv[tid] = We1[145*HH + tid];
    }
    __syncthreads();
    if (tid < HH) {
        const float* BvB = g_Bv + (b<<8)*HH;
        float a = sA[tid], u = su[tid], v = sv[tid];
        float s = 0.f, q = 0.f;
        #pragma unroll 4
        for (int j = 0; j < NN; j++) {
            float x = a + BvB[j*HH + tid] + ndn[j]*u + ndd[j]*v;
            s += x;
            q = fmaf(x, x, q);
        }
        int slot = (blockIdx.x & (NSLOT-1)) * HH + tid;
        atomicAdd(&g_esum[slot], s);
        atomicAdd(&g_esq[slot], q);
    }
}

// ---------------------------------------------------------------------------
// 3. finalize edge BN -> scale/shift
__global__ void k_fin1(const float* __restrict__ g1, const float* __restrict__ b1) {
    int c = threadIdx.x;
    if (c < HH) {
        float S = 0.f, Q = 0.f;
        for (int s = 0; s < NSLOT; s++) { S += g_esum[s*HH + c]; Q += g_esq[s*HH + c]; }
        float inv_cnt = 1.f / EDGE_CNT;
        float mu = S * inv_cnt;
        float var = Q * inv_cnt - mu*mu;
        float inv = rsqrtf(var + 1e-5f);
        float sc = g1[c] * inv;
        g_scsh1[c] = sc;
        g_scsh1[HH + c] = b1[c] - mu*sc;
    }
}

// ---------------------------------------------------------------------------
// 4. MAIN edge kernel: one block per (b,i), 256 threads (thread = j)
//    shared: We2(5184) Wx1(5184) Xs(256*73) Ms(256*73) + small
#define SM_WE2  0
#define SM_WX1  5184
#define SM_XS   10368
#define SM_MS   (SM_XS + 256*73)
#define SM_SA   (SM_MS + 256*73)
#define SM_SU   (SM_SA + 72)
#define SM_SV   (SM_SU + 72)
#define SM_SC   (SM_SV + 72)
#define SM_SH   (SM_SC + 72)
#define SM_BE2  (SM_SH + 72)
#define SM_BX1  (SM_BE2 + 72)
#define SM_WM   (SM_BX1 + 72)
#define SM_WX2  (SM_WM + 72)
#define SM_WS   (SM_WX2 + 72)
#define SM_RED  (SM_WS + 256)
#define SM_PI   (SM_RED + 32)
#define SM_TOTF (SM_PI + 4)

__global__ void k_mainedge(const float* __restrict__ p, const float* __restrict__ We1,
                           const float* __restrict__ We2, const float* __restrict__ be2,
                           const float* __restrict__ Wm,  const float* __restrict__ bm,
                           const float* __restrict__ Wx1, const float* __restrict__ bx1,
                           const float* __restrict__ Wx2, float* __restrict__ out_p) {
    extern __shared__ float sm[];
    float* sWe2 = sm + SM_WE2;
    float* sWx1 = sm + SM_WX1;
    float* Xs   = sm + SM_XS;
    float* Ms   = sm + SM_MS;
    float* sA   = sm + SM_SA;
    float* su   = sm + SM_SU;
    float* sv   = sm + SM_SV;
    float* ssc  = sm + SM_SC;
    float* ssh  = sm + SM_SH;
    float* sbe2 = sm + SM_BE2;
    float* sbx1 = sm + SM_BX1;
    float* sWm  = sm + SM_WM;
    float* sWx2 = sm + SM_WX2;
    float* ws   = sm + SM_WS;
    float* red  = sm + SM_RED;
    float* spi  = sm + SM_PI;

    int tid = threadIdx.x;
    int node = blockIdx.x;
    int b = node >> 8;

    for (int idx = tid; idx < HH*HH; idx += 256) { sWe2[idx] = We2[idx]; sWx1[idx] = Wx1[idx]; }
    if (tid < HH) {
        sA[tid]  = g_A[node*HH + tid];
        su[tid]  = We1[144*HH + tid];
        sv[tid]  = We1[145*HH + tid];
        ssc[tid] = g_scsh1[tid];
        ssh[tid] = g_scsh1[HH + tid];
        sbe2[tid] = be2[tid];
        sbx1[tid] = bx1[tid];
        sWm[tid]  = Wm[tid];
        sWx2[tid] = Wx2[tid];
    }
    if (tid < 4) spi[tid] = p[node*4 + tid];
    // Bv tile, coalesced -> padded rows
    {
        const float* BvB = g_Bv + (b<<8)*HH;
        for (int idx = tid; idx < NN*HH; idx += 256)
            Xs[(idx/HH)*73 + (idx%HH)] = BvB[idx];
    }
    float4 pj = *(const float4*)(p + ((b<<8) + tid)*4);
    __syncthreads();

    float d0 = spi[0] - pj.x, d1 = spi[1] - pj.y, d2 = spi[2] - pj.z, d3 = spi[3] - pj.w;
    float nrm = psif(-d0*d0 + d1*d1 + d2*d2 + d3*d3);
    float dot = psif(spi[0]*pj.x - spi[1]*pj.y - spi[2]*pj.z - spi[3]*pj.w);

    float* xrow = Xs + tid*73;
    #pragma unroll 4
    for (int c = 0; c < HH; c++) {
        float x = sA[c] + xrow[c] + nrm*su[c] + dot*sv[c];
        xrow[c] = fmaxf(fmaf(ssc[c], x, ssh[c]), 0.f);
    }

    // GEMM1: m = relu(x @ We2 + be2); wdot = m . Wm
    const float4* W24 = (const float4*)sWe2;
    float* mrow = Ms + tid*73;
    float wdot = 0.f;
    for (int cb = 0; cb < HH; cb += 8) {
        float a0=0.f,a1=0.f,a2=0.f,a3=0.f,a4=0.f,a5=0.f,a6=0.f,a7=0.f;
        const float4* wp = W24 + (cb>>2);
        #pragma unroll 4
        for (int k = 0; k < HH; k++) {
            float xk = xrow[k];
            float4 wa = wp[k*18];
            float4 wb = wp[k*18 + 1];
            a0 = fmaf(xk, wa.x, a0); a1 = fmaf(xk, wa.y, a1);
            a2 = fmaf(xk, wa.z, a2); a3 = fmaf(xk, wa.w, a3);
            a4 = fmaf(xk, wb.x, a4); a5 = fmaf(xk, wb.y, a5);
            a6 = fmaf(xk, wb.z, a6); a7 = fmaf(xk, wb.w, a7);
        }
        float m;
        m = fmaxf(a0 + sbe2[cb+0], 0.f); mrow[cb+0] = m; wdot = fmaf(m, sWm[cb+0], wdot);
        m = fmaxf(a1 + sbe2[cb+1], 0.f); mrow[cb+1] = m; wdot = fmaf(m, sWm[cb+1], wdot);
        m = fmaxf(a2 + sbe2[cb+2], 0.f); mrow[cb+2] = m; wdot = fmaf(m, sWm[cb+2], wdot);
        m = fmaxf(a3 + sbe2[cb+3], 0.f); mrow[cb+3] = m; wdot = fmaf(m, sWm[cb+3], wdot);
        m = fmaxf(a4 + sbe2[cb+4], 0.f); mrow[cb+4] = m; wdot = fmaf(m, sWm[cb+4], wdot);
        m = fmaxf(a5 + sbe2[cb+5], 0.f); mrow[cb+5] = m; wdot = fmaf(m, sWm[cb+5], wdot);
        m = fmaxf(a6 + sbe2[cb+6], 0.f); mrow[cb+6] = m; wdot = fmaf(m, sWm[cb+6], wdot);
        m = fmaxf(a7 + sbe2[cb+7], 0.f); mrow[cb+7] = m; wdot = fmaf(m, sWm[cb+7], wdot);
    }
    float w = 1.f / (1.f + expf(-(wdot + bm[0])));
    ws[tid] = w;

    // GEMM2: t = relu(w*(m@Wx1)+bx1); xw = t . Wx2
    const float4* W14 = (const float4*)sWx1;
    float xw = 0.f;
    for (int cb = 0; cb < HH; cb += 8) {
        float a0=0.f,a1=0.f,a2=0.f,a3=0.f,a4=0.f,a5=0.f,a6=0.f,a7=0.f;
        const float4* wp = W14 + (cb>>2);
        #pragma unroll 4
        for (int k = 0; k < HH; k++) {
            float mk = mrow[k];
            float4 wa = wp[k*18];
            float4 wb = wp[k*18 + 1];
            a0 = fmaf(mk, wa.x, a0); a1 = fmaf(mk, wa.y, a1);
            a2 = fmaf(mk, wa.z, a2); a3 = fmaf(mk, wa.w, a3);
            a4 = fmaf(mk, wb.x, a4); a5 = fmaf(mk, wb.y, a5);
            a6 = fmaf(mk, wb.z, a6); a7 = fmaf(mk, wb.w, a7);
        }
        float t;
        t = fmaxf(fmaf(w, a0, sbx1[cb+0]), 0.f); xw = fmaf(t, sWx2[cb+0], xw);
        t = fmaxf(fmaf(w, a1, sbx1[cb+1]), 0.f); xw = fmaf(t, sWx2[cb+1], xw);
        t = fmaxf(fmaf(w, a2, sbx1[cb+2]), 0.f); xw = fmaf(t, sWx2[cb+2], xw);
        t = fmaxf(fmaf(w, a3, sbx1[cb+3]), 0.f); xw = fmaf(t, sWx2[cb+3], xw);
        t = fmaxf(fmaf(w, a4, sbx1[cb+4]), 0.f); xw = fmaf(t, sWx2[cb+4], xw);
        t = fmaxf(fmaf(w, a5, sbx1[cb+5]), 0.f); xw = fmaf(t, sWx2[cb+5], xw);
        t = fmaxf(fmaf(w, a6, sbx1[cb+6]), 0.f); xw = fmaf(t, sWx2[cb+6], xw);
        t = fmaxf(fmaf(w, a7, sbx1[cb+7]), 0.f); xw = fmaf(t, sWx2[cb+7], xw);
    }

    // aggs: mean_j clip(p_diff * xw)
    float q0 = fminf(fmaxf(d0*xw, -100.f), 100.f);
    float q1 = fminf(fmaxf(d1*xw, -100.f), 100.f);
    float q2 = fminf(fmaxf(d2*xw, -100.f), 100.f);
    float q3 = fminf(fmaxf(d3*xw, -100.f), 100.f);
    #pragma unroll
    for (int o = 16; o > 0; o >>= 1) {
        q0 += __shfl_down_sync(0xffffffffu, q0, o);
        q1 += __shfl_down_sync(0xffffffffu, q1, o);
        q2 += __shfl_down_sync(0xffffffffu, q2, o);
        q3 += __shfl_down_sync(0xffffffffu, q3, o);
    }
    int lane = tid & 31, wrp = tid >> 5;
    if (lane == 0) { red[wrp*4+0]=q0; red[wrp*4+1]=q1; red[wrp*4+2]=q2; red[wrp*4+3]=q3; }
    __syncthreads();   // also gates Ms/ws for magg phase
    if (tid < 4) {
        float s = 0.f;
        #pragma unroll
        for (int wq = 0; wq < 8; wq++) s += red[wq*4 + tid];
        out_p[node*4 + tid] = spi[tid] + (s * (1.f/256.f)) * 0.001f;
    }
    // magg_c = sum_j m[j][c] * w[j]
    if (tid < HH) {
        float acc = 0.f;
        #pragma unroll 4
        for (int j = 0; j < NN; j++) acc = fmaf(Ms[j*73 + tid], ws[j], acc);
        g_magg[node*HH + tid] = acc;
    }
}

// ---------------------------------------------------------------------------
// 5. node stats: y = [h, magg, s] @ Wh1 + bh1 ; accumulate BN stats
__global__ void k_nodestats(const float* __restrict__ h, const float* __restrict__ s_in,
                            const float* __restrict__ Wh1, const float* __restrict__ bh1) {
    __shared__ float hins[2*HH + SS];
    int node = blockIdx.x;
    int tid = threadIdx.x;           // 128
    for (int idx = tid; idx < HH; idx += 128) {
        hins[idx]      = h[node*HH + idx];
        hins[HH + idx] = g_magg[node*HH + idx];
    }
    if (tid < SS) hins[2*HH + tid] = s_in[node*SS + tid];
    __syncthreads();
    if (tid < HH) {
        float acc = bh1[tid];
        #pragma unroll 4
        for (int k = 0; k < 2*HH + SS; k++)
            acc = fmaf(hins[k], Wh1[k*HH + tid], acc);
        g_y[node*HH + tid] = acc;
        int slot = (blockIdx.x & (NSLOT-1)) * HH + tid;
        atomicAdd(&g_nsum[slot], acc);
        atomicAdd(&g_nsq[slot], acc*acc);
    }
}

// ---------------------------------------------------------------------------
// 6. finalize node BN
__global__ void k_fin2(const float* __restrict__ gh, const float* __restrict__ bh) {
    int c = threadIdx.x;
    if (c < HH) {
        float S = 0.f, Q = 0.f;
        for (int s = 0; s < NSLOT; s++) { S += g_nsum[s*HH + c]; Q += g_nsq[s*HH + c]; }
        float inv_cnt = 1.f / (float)NODES;
        float mu = S * inv_cnt;
        float var = Q * inv_cnt - mu*mu;
        float inv = rsqrtf(var + 1e-5f);
        float sc = gh[c] * inv;
        g_scsh2[c] = sc;
        g_scsh2[HH + c] = bh[c] - mu*sc;
    }
}

// ---------------------------------------------------------------------------
// 7. h_out = h + relu(BN(y)) @ Wh2 + bh2
__global__ void k_hout(const float* __restrict__ h, const float* __restrict__ Wh2,
                       const float* __restrict__ bh2, float* __restrict__ out_h) {
    __shared__ float yr[HH];
    int node = blockIdx.x;
    int c = threadIdx.x;
    if (c < HH)
        yr[c] = fmaxf(fmaf(g_scsh2[c], g_y[node*HH + c], g_scsh2[HH + c]), 0.f);
    __syncthreads();
    if (c < HH) {
        float acc = bh2[c] + h[node*HH + c];
        #pragma unroll 4
        for (int k = 0; k < HH; k++)
            acc = fmaf(yr[k], Wh2[k*HH + c], acc);
        out_h[node*HH + c] = acc;
    }
}

// ---------------------------------------------------------------------------
extern "C" void kernel_launch(void* const* d_in, const int* in_sizes, int n_in,
                              void* d_out, int out_size) {
    const float* h   = (const float*)d_in[0];
    const float* p   = (const float*)d_in[1];
    const float* s   = (const float*)d_in[2];
    const float* We1 = (const float*)d_in[3];
    const float* g1  = (const float*)d_in[4];
    const float* b1  = (const float*)d_in[5];
    const float* We2 = (const float*)d_in[6];
    const float* be2 = (const float*)d_in[7];
    const float* Wm  = (const float*)d_in[8];
    const float* bm  = (const float*)d_in[9];
    const float* Wx1 = (const float*)d_in[10];
    const float* bx1 = (const float*)d_in[11];
    const float* Wx2 = (const float*)d_in[12];
    const float* Wh1 = (const float*)d_in[13];
    const float* bh1 = (const float*)d_in[14];
    const float* gh  = (const float*)d_in[15];
    const float* bh  = (const float*)d_in[16];
    const float* Wh2 = (const float*)d_in[17];
    const float* bh2 = (const float*)d_in[18];

    float* out_h = (float*)d_out;                       // (B,N,H)
    float* out_p = (float*)d_out + NODES*HH;            // (B,N,4)

    size_t smem_main = (size_t)SM_TOTF * sizeof(float); // ~195 KB
    cudaFuncSetAttribute(k_mainedge, cudaFuncAttributeMaxDynamicSharedMemorySize,
                         (int)smem_main);

    k_zero<<<(NSLOT*HH + 255)/256, 256>>>();
    k_nodepre<<<NODES, 96>>>(h, We1);
    k_edgestats<<<NODES, 128>>>(p, We1);
    k_fin1<<<1, HH>>>(g1, b1);
    k_mainedge<<<NODES, 256, smem_main>>>(p, We1, We2, be2, Wm, bm, Wx1, bx1, Wx2, out_p);
    k_nodestats<<<NODES, 128>>>(h, s, Wh1, bh1);
    k_fin2<<<1, HH>>>(gh, bh);
    k_hout<<<NODES, 96>>>(h, Wh2, bh2, out_h);
}

// round 8
// speedup vs baseline: 2.4121x; 2.4121x over previous
#include <cuda_runtime.h>
#include <cuda_bf16.h>
#include <math.h>

// Problem constants
#define BB 16
#define NN 256
#define HH 72
#define SS 13
#define NODES (BB*NN)          // 4096
#define EDGE_CNT ((float)(BB)*(float)(NN)*(float)(NN))  // 1048576
#define NSLOT 64

// Scratch (device globals; no allocation allowed)
__device__ float g_A[NODES*HH];
__device__ float g_Bv[NODES*HH];
__device__ float g_magg[NODES*HH];
__device__ float g_y[NODES*HH];
__device__ float g_esum[NSLOT*HH];
__device__ float g_esq[NSLOT*HH];
__device__ float g_nsum[NSLOT*HH];
__device__ float g_nsq[NSLOT*HH];
__device__ float g_scsh1[2*HH];
__device__ float g_scsh2[2*HH];

__device__ __forceinline__ float psif(float x) {
    return copysignf(log1pf(fabsf(x)), x);
}

// ---- packed f32x2 helpers (sm_103a FFMA2) ----
__device__ __forceinline__ void ffma2(unsigned long long &d,
                                      unsigned long long a, unsigned long long b) {
    asm("fma.rn.f32x2 %0, %1, %2, %0;" : "+l"(d) : "l"(a), "l"(b));
}
__device__ __forceinline__ unsigned long long dup2(float x) {
    unsigned long long r; unsigned u = __float_as_uint(x);
    asm("mov.b64 %0, {%1, %1};" : "=l"(r) : "r"(u));
    return r;
}
__device__ __forceinline__ float2 unp2(unsigned long long v) {
    unsigned lo, hi;
    asm("mov.b64 {%0, %1}, %2;" : "=r"(lo), "=r"(hi) : "l"(v));
    return make_float2(__uint_as_float(lo), __uint_as_float(hi));
}

// ---------------------------------------------------------------------------
// 0. zero slot accumulators
__global__ void k_zero() {
    int i = blockIdx.x * blockDim.x + threadIdx.x;
    if (i < NSLOT*HH) { g_esum[i]=0.f; g_esq[i]=0.f; g_nsum[i]=0.f; g_nsq[i]=0.f; }
}

// ---------------------------------------------------------------------------
// 1. node pre: A = h @ We1[0:72], Bv = h @ We1[72:144]
__global__ void k_nodepre(const float* __restrict__ h, const float* __restrict__ We1) {
    __shared__ float hs[HH];
    int node = blockIdx.x;
    int c = threadIdx.x;
    if (c < HH) hs[c] = h[node*HH + c];
    __syncthreads();
    if (c < HH) {
        float a = 0.f, b = 0.f;
        #pragma unroll 4
        for (int k = 0; k < HH; k++) {
            float hv = hs[k];
            a = fmaf(hv, We1[k*HH + c], a);
            b = fmaf(hv, We1[(k+HH)*HH + c], b);
        }
        g_A[node*HH + c] = a;
        g_Bv[node*HH + c] = b;
    }
}

// ---------------------------------------------------------------------------
// 2. edge stats: per-channel sum and sumsq of x over all B*N*N edges
__global__ void k_edgestats(const float* __restrict__ p, const float* __restrict__ We1) {
    __shared__ float ndn[NN], ndd[NN];
    __shared__ float sA[HH], su[HH], sv[HH];
    int node = blockIdx.x;           // (b,i)
    int b = node >> 8;
    int tid = threadIdx.x;           // 128 threads

    float4 pi4 = *(const float4*)(p + node*4);
    for (int jj = tid; jj < NN; jj += 128) {
        float4 pj = *(const float4*)(p + ((b<<8) + jj)*4);
        float d0 = pi4.x - pj.x, d1 = pi4.y - pj.y, d2 = pi4.z - pj.z, d3 = pi4.w - pj.w;
        ndn[jj] = psif(-d0*d0 + d1*d1 + d2*d2 + d3*d3);
        ndd[jj] = psif(pi4.x*pj.x - pi4.y*pj.y - pi4.z*pj.z - pi4.w*pj.w);
    }
    if (tid < HH) {
        sA[tid] = g_A[node*HH + tid];
        su[tid] = We1[144*HH + tid];
        sv[tid] = We1[145*HH + tid];
    }
    __syncthreads();
    if (tid < HH) {
        const float* BvB = g_Bv + (b<<8)*HH;
        float a = sA[tid], u = su[tid], v = sv[tid];
        float s = 0.f, q = 0.f;
        #pragma unroll 4
        for (int j = 0; j < NN; j++) {
            float x = a + BvB[j*HH + tid] + ndn[j]*u + ndd[j]*v;
            s += x;
            q = fmaf(x, x, q);
        }
        int slot = (blockIdx.x & (NSLOT-1)) * HH + tid;
        atomicAdd(&g_esum[slot], s);
        atomicAdd(&g_esq[slot], q);
    }
}

// ---------------------------------------------------------------------------
// 3. finalize edge BN -> scale/shift
__global__ void k_fin1(const float* __restrict__ g1, const float* __restrict__ b1) {
    int c = threadIdx.x;
    if (c < HH) {
        float S = 0.f, Q = 0.f;
        #pragma unroll 8
        for (int s = 0; s < NSLOT; s++) { S += g_esum[s*HH + c]; Q += g_esq[s*HH + c]; }
        float inv_cnt = 1.f / EDGE_CNT;
        float mu = S * inv_cnt;
        float var = Q * inv_cnt - mu*mu;
        float inv = rsqrtf(var + 1e-5f);
        float sc = g1[c] * inv;
        g_scsh1[c] = sc;
        g_scsh1[HH + c] = b1[c] - mu*sc;
    }
}

// ---------------------------------------------------------------------------
// 4. MAIN edge kernel: one block per (b,i), 512 threads
//    GEMMs register-tiled: warp w -> colgroup cg=w&7 (cols 10*cg..10*cg+9,
//    padded to 80), half = w>>3 (rows half*128 + 4*lane .. +3).
//    X and M stored k-major (stride 260) so rows load as float4.
//    Weights packed [k][8 groups][12] (10 used + 2 pad), loaded as f64 pairs.

#define XTS 260
#define OF_W2   0
#define OF_W1   6912
#define OF_XT   13824
#define OF_MT   32544           /* aliased with Bs (256*73) during phase A */
#define OF_PD   51264           /* pd[4][256] */
#define OF_WP   52288           /* wpart / xwpart [8][256] */
#define OF_WS   54336           /* ws[256] */
#define OF_SA   54592
#define OF_SU   54664
#define OF_SV   54736
#define OF_SC   54808
#define OF_SH   54880
#define OF_BE2  54952
#define OF_BX1  55024
#define OF_WM   55096
#define OF_WX2  55168
#define OF_MG   55240           /* maggp[2][72] */
#define OF_RED  55384           /* red[32] */
#define OF_SPI  55416           /* spi[4] */
#define TOT_F   55420           /* *4 = 221680 bytes */

__device__ __forceinline__ void gemm_tile(const float* __restrict__ xcol,
                                          const float* __restrict__ wrow,
                                          unsigned long long acc[4][5]) {
    #pragma unroll 2
    for (int k = 0; k < HH; k++) {
        float4 xv = *(const float4*)xcol; xcol += XTS;
        double2 wa = *(const double2*)wrow;
        double2 wb = *(const double2*)(wrow + 4);
        double  wc = *(const double*)(wrow + 8);
        wrow += 96;
        unsigned long long w0 = __double_as_longlong(wa.x);
        unsigned long long w1 = __double_as_longlong(wa.y);
        unsigned long long w2 = __double_as_longlong(wb.x);
        unsigned long long w3 = __double_as_longlong(wb.y);
        unsigned long long w4 = __double_as_longlong(wc);
        unsigned long long x0 = dup2(xv.x), x1 = dup2(xv.y),
                           x2 = dup2(xv.z), x3 = dup2(xv.w);
        ffma2(acc[0][0],x0,w0); ffma2(acc[0][1],x0,w1); ffma2(acc[0][2],x0,w2);
        ffma2(acc[0][3],x0,w3); ffma2(acc[0][4],x0,w4);
        ffma2(acc[1][0],x1,w0); ffma2(acc[1][1],x1,w1); ffma2(acc[1][2],x1,w2);
        ffma2(acc[1][3],x1,w3); ffma2(acc[1][4],x1,w4);
        ffma2(acc[2][0],x2,w0); ffma2(acc[2][1],x2,w1); ffma2(acc[2][2],x2,w2);
        ffma2(acc[2][3],x2,w3); ffma2(acc[2][4],x2,w4);
        ffma2(acc[3][0],x3,w0); ffma2(acc[3][1],x3,w1); ffma2(acc[3][2],x3,w2);
        ffma2(acc[3][3],x3,w3); ffma2(acc[3][4],x3,w4);
    }
}

__global__ void __launch_bounds__(512, 1)
k_mainedge(const float* __restrict__ p, const float* __restrict__ We1,
           const float* __restrict__ We2, const float* __restrict__ be2,
           const float* __restrict__ Wm,  const float* __restrict__ bm,
           const float* __restrict__ Wx1, const float* __restrict__ bx1,
           const float* __restrict__ Wx2, float* __restrict__ out_p) {
    extern __shared__ float sm[];
    float* sW2  = sm + OF_W2;
    float* sW1  = sm + OF_W1;
    float* Xt   = sm + OF_XT;
    float* Mt   = sm + OF_MT;     // also Bs (stride 73) in phase A
    float* pd   = sm + OF_PD;
    float* wpart= sm + OF_WP;
    float* ws   = sm + OF_WS;
    float* sA   = sm + OF_SA;
    float* su   = sm + OF_SU;
    float* sv   = sm + OF_SV;
    float* ssc  = sm + OF_SC;
    float* ssh  = sm + OF_SH;
    float* sbe2 = sm + OF_BE2;
    float* sbx1 = sm + OF_BX1;
    float* sWm  = sm + OF_WM;
    float* sWx2 = sm + OF_WX2;
    float* maggp= sm + OF_MG;
    float* red  = sm + OF_RED;
    float* spi  = sm + OF_SPI;

    int tid  = threadIdx.x;
    int wid  = tid >> 5;
    int lane = tid & 31;
    int node = blockIdx.x;
    int b    = node >> 8;

    // ---- phase A0: stage Bv (coalesced -> padded 73) and pack weights ----
    {
        const float* BvB = g_Bv + (b<<8)*HH;
        for (int idx = tid; idx < NN*HH; idx += 512)
            Mt[(idx/HH)*73 + (idx%HH)] = BvB[idx];   // Bs
        for (int idx = tid; idx < HH*96; idx += 512) {
            int k = idx/96, rem = idx%96, cg = rem/12, i = rem%12;
            int col = cg*10 + i;
            bool ok = (i < 10) && (col < HH);
            sW2[idx] = ok ? We2[k*HH + col] : 0.f;
            sW1[idx] = ok ? Wx1[k*HH + col] : 0.f;
        }
    }
    if (tid < HH) {
        sA[tid]  = g_A[node*HH + tid];
        su[tid]  = We1[144*HH + tid];
        sv[tid]  = We1[145*HH + tid];
        ssc[tid] = g_scsh1[tid];
        ssh[tid] = g_scsh1[HH + tid];
        sbe2[tid] = be2[tid];
        sbx1[tid] = bx1[tid];
        sWm[tid]  = Wm[tid];
        sWx2[tid] = Wx2[tid];
    }
    if (tid < 4) spi[tid] = p[node*4 + tid];
    __syncthreads();

    // ---- phase A1: build Xt[k][j] = relu(BN(x)) , pd[q][j] ----
    if (tid < NN) {
        int j = tid;
        float pi0 = spi[0], pi1 = spi[1], pi2 = spi[2], pi3 = spi[3];
        float4 pj = *(const float4*)(p + ((b<<8) + j)*4);
        float d0 = pi0 - pj.x, d1 = pi1 - pj.y, d2 = pi2 - pj.z, d3 = pi3 - pj.w;
        pd[0*NN+j] = d0; pd[1*NN+j] = d1; pd[2*NN+j] = d2; pd[3*NN+j] = d3;
        float nrm = psif(-d0*d0 + d1*d1 + d2*d2 + d3*d3);
        float dot = psif(pi0*pj.x - pi1*pj.y - pi2*pj.z - pi3*pj.w);
        const float* Bs = Mt + j*73;
        #pragma unroll 4
        for (int c = 0; c < HH; c++) {
            float x = sA[c] + Bs[c] + nrm*su[c] + dot*sv[c];
            Xt[c*XTS + j] = fmaxf(fmaf(ssc[c], x, ssh[c]), 0.f);
        }
    }
    __syncthreads();

    // ---- GEMM1: M = relu(X @ We2 + be2); wpart = partial m.Wm ----
    int cg   = wid & 7;
    int half = wid >> 3;
    int r0   = half*128 + 4*lane;
    {
        unsigned long long acc[4][5];
        #pragma unroll
        for (int r = 0; r < 4; r++)
            #pragma unroll
            for (int q = 0; q < 5; q++) acc[r][q] = 0ull;
        gemm_tile(Xt + r0, sW2 + cg*12, acc);

        float ws0=0.f, ws1=0.f, ws2=0.f, ws3=0.f;
        #pragma unroll
        for (int q = 0; q < 5; q++) {
            int c0 = cg*10 + 2*q, c1 = c0 + 1;
            float2 v0 = unp2(acc[0][q]), v1 = unp2(acc[1][q]),
                   v2 = unp2(acc[2][q]), v3 = unp2(acc[3][q]);
            if (c0 < HH) {
                float be = sbe2[c0], wm = sWm[c0];
                float4 mv;
                mv.x = fmaxf(v0.x + be, 0.f); mv.y = fmaxf(v1.x + be, 0.f);
                mv.z = fmaxf(v2.x + be, 0.f); mv.w = fmaxf(v3.x + be, 0.f);
                *(float4*)&Mt[c0*XTS + r0] = mv;
                ws0 = fmaf(mv.x, wm, ws0); ws1 = fmaf(mv.y, wm, ws1);
                ws2 = fmaf(mv.z, wm, ws2); ws3 = fmaf(mv.w, wm, ws3);
            }
            if (c1 < HH) {
                float be = sbe2[c1], wm = sWm[c1];
                float4 mv;
                mv.x = fmaxf(v0.y + be, 0.f); mv.y = fmaxf(v1.y + be, 0.f);
                mv.z = fmaxf(v2.y + be, 0.f); mv.w = fmaxf(v3.y + be, 0.f);
                *(float4*)&Mt[c1*XTS + r0] = mv;
                ws0 = fmaf(mv.x, wm, ws0); ws1 = fmaf(mv.y, wm, ws1);
                ws2 = fmaf(mv.z, wm, ws2); ws3 = fmaf(mv.w, wm, ws3);
            }
        }
        float4 wv; wv.x=ws0; wv.y=ws1; wv.z=ws2; wv.w=ws3;
        *(float4*)&wpart[cg*NN + r0] = wv;
    }
    __syncthreads();

    // ---- w = sigmoid(sum wpart + bm) ----
    if (tid < NN) {
        float s = bm[0];
        #pragma unroll
        for (int g = 0; g < 8; g++) s += wpart[g*NN + tid];
        ws[tid] = 1.f / (1.f + expf(-s));
    }
    __syncthreads();

    // ---- GEMM2: t = relu(w*(M @ Wx1) + bx1); xwpart = partial t.Wx2 ----
    {
        unsigned long long acc[4][5];
        #pragma unroll
        for (int r = 0; r < 4; r++)
            #pragma unroll
            for (int q = 0; q < 5; q++) acc[r][q] = 0ull;
        gemm_tile(Mt + r0, sW1 + cg*12, acc);

        float4 wr4 = *(const float4*)&ws[r0];
        float xs0=0.f, xs1=0.f, xs2=0.f, xs3=0.f;
        #pragma unroll
        for (int q = 0; q < 5; q++) {
            int c0 = cg*10 + 2*q, c1 = c0 + 1;
            float2 v0 = unp2(acc[0][q]), v1 = unp2(acc[1][q]),
                   v2 = unp2(acc[2][q]), v3 = unp2(acc[3][q]);
            if (c0 < HH) {
                float bx = sbx1[c0], w2 = sWx2[c0];
                xs0 = fmaf(fmaxf(fmaf(wr4.x, v0.x, bx), 0.f), w2, xs0);
                xs1 = fmaf(fmaxf(fmaf(wr4.y, v1.x, bx), 0.f), w2, xs1);
                xs2 = fmaf(fmaxf(fmaf(wr4.z, v2.x, bx), 0.f), w2, xs2);
                xs3 = fmaf(fmaxf(fmaf(wr4.w, v3.x, bx), 0.f), w2, xs3);
            }
            if (c1 < HH) {
                float bx = sbx1[c1], w2 = sWx2[c1];
                xs0 = fmaf(fmaxf(fmaf(wr4.x, v0.y, bx), 0.f), w2, xs0);
                xs1 = fmaf(fmaxf(fmaf(wr4.y, v1.y, bx), 0.f), w2, xs1);
                xs2 = fmaf(fmaxf(fmaf(wr4.z, v2.y, bx), 0.f), w2, xs2);
                xs3 = fmaf(fmaxf(fmaf(wr4.w, v3.y, bx), 0.f), w2, xs3);
            }
        }
        float4 xv; xv.x=xs0; xv.y=xs1; xv.z=xs2; xv.w=xs3;
        *(float4*)&wpart[cg*NN + r0] = xv;   // now xwpart
    }
    __syncthreads();

    // ---- epilogue: aggs reduction (threads 0..255) + magg (threads 256..399) ----
    if (tid < NN) {
        float xw = 0.f;
        #pragma unroll
        for (int g = 0; g < 8; g++) xw += wpart[g*NN + tid];
        float q0 = fminf(fmaxf(pd[0*NN+tid]*xw, -100.f), 100.f);
        float q1 = fminf(fmaxf(pd[1*NN+tid]*xw, -100.f), 100.f);
        float q2 = fminf(fmaxf(pd[2*NN+tid]*xw, -100.f), 100.f);
        float q3 = fminf(fmaxf(pd[3*NN+tid]*xw, -100.f), 100.f);
        #pragma unroll
        for (int o = 16; o > 0; o >>= 1) {
            q0 += __shfl_down_sync(0xffffffffu, q0, o);
            q1 += __shfl_down_sync(0xffffffffu, q1, o);
            q2 += __shfl_down_sync(0xffffffffu, q2, o);
            q3 += __shfl_down_sync(0xffffffffu, q3, o);
        }
        if (lane == 0) { red[wid*4+0]=q0; red[wid*4+1]=q1; red[wid*4+2]=q2; red[wid*4+3]=q3; }
    } else if (tid < NN + 144) {
        int u = tid - NN;
        int c = u % HH, g = u / HH;          // g in {0,1}
        float acc = 0.f;
        const float* mrow = Mt + c*XTS + g*128;
        const float* wv = ws + g*128;
        #pragma unroll 4
        for (int j = 0; j < 128; j++) acc = fmaf(mrow[j], wv[j], acc);
        maggp[g*HH + c] = acc;
    }
    __syncthreads();
    if (tid < 4) {
        float s = 0.f;
        #pragma unroll
        for (int wq = 0; wq < 8; wq++) s += red[wq*4 + tid];
        out_p[node*4 + tid] = spi[tid] + (s * (1.f/256.f)) * 0.001f;
    }
    if (tid < HH) g_magg[node*HH + tid] = maggp[tid] + maggp[HH + tid];
}

// ---------------------------------------------------------------------------
// 5. node stats: y = [h, magg, s] @ Wh1 + bh1 ; accumulate BN stats
__global__ void k_nodestats(const float* __restrict__ h, const float* __restrict__ s_in,
                            const float* __restrict__ Wh1, const float* __restrict__ bh1) {
    __shared__ float hins[2*HH + SS];
    int node = blockIdx.x;
    int tid = threadIdx.x;           // 128
    for (int idx = tid; idx < HH; idx += 128) {
        hins[idx]      = h[node*HH + idx];
        hins[HH + idx] = g_magg[node*HH + idx];
    }
    if (tid < SS) hins[2*HH + tid] = s_in[node*SS + tid];
    __syncthreads();
    if (tid < HH) {
        float acc = bh1[tid];
        #pragma unroll 4
        for (int k = 0; k < 2*HH + SS; k++)
            acc = fmaf(hins[k], Wh1[k*HH + tid], acc);
        g_y[node*HH + tid] = acc;
        int slot = (blockIdx.x & (NSLOT-1)) * HH + tid;
        atomicAdd(&g_nsum[slot], acc);
        atomicAdd(&g_nsq[slot], acc*acc);
    }
}

// ---------------------------------------------------------------------------
// 6. finalize node BN
__global__ void k_fin2(const float* __restrict__ gh, const float* __restrict__ bh) {
    int c = threadIdx.x;
    if (c < HH) {
        float S = 0.f, Q = 0.f;
        #pragma unroll 8
        for (int s = 0; s < NSLOT; s++) { S += g_nsum[s*HH + c]; Q += g_nsq[s*HH + c]; }
        float inv_cnt = 1.f / (float)NODES;
        float mu = S * inv_cnt;
        float var = Q * inv_cnt - mu*mu;
        float inv = rsqrtf(var + 1e-5f);
        float sc = gh[c] * inv;
        g_scsh2[c] = sc;
        g_scsh2[HH + c] = bh[c] - mu*sc;
    }
}

// ---------------------------------------------------------------------------
// 7. h_out = h + relu(BN(y)) @ Wh2 + bh2
__global__ void k_hout(const float* __restrict__ h, const float* __restrict__ Wh2,
                       const float* __restrict__ bh2, float* __restrict__ out_h) {
    __shared__ float yr[HH];
    int node = blockIdx.x;
    int c = threadIdx.x;
    if (c < HH)
        yr[c] = fmaxf(fmaf(g_scsh2[c], g_y[node*HH + c], g_scsh2[HH + c]), 0.f);
    __syncthreads();
    if (c < HH) {
        float acc = bh2[c] + h[node*HH + c];
        #pragma unroll 4
        for (int k = 0; k < HH; k++)
            acc = fmaf(yr[k], Wh2[k*HH + c], acc);
        out_h[node*HH + c] = acc;
    }
}

// ---------------------------------------------------------------------------
extern "C" void kernel_launch(void* const* d_in, const int* in_sizes, int n_in,
                              void* d_out, int out_size) {
    const float* h   = (const float*)d_in[0];
    const float* p   = (const float*)d_in[1];
    const float* s   = (const float*)d_in[2];
    const float* We1 = (const float*)d_in[3];
    const float* g1  = (const float*)d_in[4];
    const float* b1  = (const float*)d_in[5];
    const float* We2 = (const float*)d_in[6];
    const float* be2 = (const float*)d_in[7];
    const float* Wm  = (const float*)d_in[8];
    const float* bm  = (const float*)d_in[9];
    const float* Wx1 = (const float*)d_in[10];
    const float* bx1 = (const float*)d_in[11];
    const float* Wx2 = (const float*)d_in[12];
    const float* Wh1 = (const float*)d_in[13];
    const float* bh1 = (const float*)d_in[14];
    const float* gh  = (const float*)d_in[15];
    const float* bh  = (const float*)d_in[16];
    const float* Wh2 = (const float*)d_in[17];
    const float* bh2 = (const float*)d_in[18];

    float* out_h = (float*)d_out;                       // (B,N,H)
    float* out_p = (float*)d_out + NODES*HH;            // (B,N,4)

    size_t smem_main = (size_t)TOT_F * sizeof(float);   // ~216.5 KB
    cudaFuncSetAttribute(k_mainedge, cudaFuncAttributeMaxDynamicSharedMemorySize,
                         (int)smem_main);

    k_zero<<<(NSLOT*HH + 255)/256, 256>>>();
    k_nodepre<<<NODES, 96>>>(h, We1);
    k_edgestats<<<NODES, 128>>>(p, We1);
    k_fin1<<<1, HH>>>(g1, b1);
    k_mainedge<<<NODES, 512, smem_main>>>(p, We1, We2, be2, Wm, bm, Wx1, bx1, Wx2, out_p);
    k_nodestats<<<NODES, 128>>>(h, s, Wh1, bh1);
    k_fin2<<<1, HH>>>(gh, bh);
    k_hout<<<NODES, 96>>>(h, Wh2, bh2, out_h);
}